// round 11
// baseline (speedup 1.0000x reference)
#include <cuda_runtime.h>
#include <math.h>
#include <stdint.h>

// Problem constants
#define Bq   64
#define Tt   256
#define Ss   512
#define Hh   1024
#define G4H  4096
#define HD   512
#define Aa   64
#define NOUT 64
#define MROWS (Bq * Tt)   // 16384
#define NBLK 128

// ---------------- scratch (device globals; no runtime allocation) ----------
__device__ float g_xp[(size_t)MROWS * G4H];   // [B*T, 4H] input projection (+bias)
__device__ float g_hT[2][Hh * Bq];            // ping-pong hidden state, TRANSPOSED [k][m]
__device__ float g_hid[Bq * HD];              // relu dense head
__device__ unsigned g_bar;                    // grid barrier counter

// Dynamic smem partition (floats):
//   ws [1024][32]  : 0      .. 32767   (131072 B)
//   sh [64][64]    : 32768  .. 36863   (16384 B)
//   zs [64][34]    : 36864  .. 39039   (8704 B)
#define SMEM_FLOATS 39040
#define SMEM_BYTES  (SMEM_FLOATS * 4)

// =====================================================================
// Kernel 1: x_proj = x @ W_x + b     (M=16384, N=4096, K=512)
// (unchanged from passing R3 kernel)
// =====================================================================
__global__ __launch_bounds__(256) void k_xproj(const float* __restrict__ X,
                                               const float* __restrict__ Wx,
                                               const float* __restrict__ bias)
{
    __shared__ float As[16][64];      // [k][m]
    __shared__ float Bs[16][64];      // [k][n]

    const int bn = blockIdx.x * 64;
    const int bm = blockIdx.y * 64;
    const int tid = threadIdx.x;
    const int tx = tid & 15;
    const int ty = tid >> 4;

    float acc[4][4];
#pragma unroll
    for (int i = 0; i < 4; i++)
#pragma unroll
        for (int j = 0; j < 4; j++) acc[i][j] = 0.f;

    const int ar = tid >> 2;
    const int ak = (tid & 3) * 4;
    const int bk = tid >> 4;
    const int bc = (tid & 15) * 4;

    for (int k0 = 0; k0 < Ss; k0 += 16) {
        float4 av = *(const float4*)(X + (size_t)(bm + ar) * Ss + k0 + ak);
        float4 bv = *(const float4*)(Wx + (size_t)(k0 + bk) * G4H + bn + bc);
        As[ak + 0][ar] = av.x;
        As[ak + 1][ar] = av.y;
        As[ak + 2][ar] = av.z;
        As[ak + 3][ar] = av.w;
        *(float4*)&Bs[bk][bc] = bv;
        __syncthreads();
#pragma unroll
        for (int kk = 0; kk < 16; kk++) {
            float a[4], b[4];
#pragma unroll
            for (int i = 0; i < 4; i++) a[i] = As[kk][ty * 4 + i];
#pragma unroll
            for (int j = 0; j < 4; j++) b[j] = Bs[kk][tx * 4 + j];
#pragma unroll
            for (int i = 0; i < 4; i++)
#pragma unroll
                for (int j = 0; j < 4; j++)
                    acc[i][j] = fmaf(a[i], b[j], acc[i][j]);
        }
        __syncthreads();
    }

    const int col = bn + tx * 4;
    float4 bv = *(const float4*)(bias + col);
#pragma unroll
    for (int i = 0; i < 4; i++) {
        const size_t row = bm + ty * 4 + i;
        float4 o;
        o.x = acc[i][0] + bv.x;
        o.y = acc[i][1] + bv.y;
        o.z = acc[i][2] + bv.z;
        o.w = acc[i][3] + bv.w;
        *(float4*)(g_xp + row * G4H + col) = o;
    }
}

// =====================================================================
// Kernel 2: persistent LSTM recurrence. 128 blocks (one per SM),
// 256 threads. Block b owns hidden units j0=8b..8b+7 (32 z-columns over
// 4 gates). W_h columns live in smem for the whole kernel. h is stored
// transposed [k][m] in global, ping-pong. One grid barrier per step.
// Inner product uses packed fma.rn.f32x2 on row-pairs.
// =====================================================================
__global__ __launch_bounds__(256, 1) void k_persist(const float* __restrict__ Wh)
{
    extern __shared__ float smem[];
    float* ws = smem;              // [1024][32]
    float* sh = smem + 32768;      // [64][64]  h chunk, [k][m]
    float* zs = smem + 36864;      // [64][34]  z tile, padded

    const int tid = threadIdx.x;
    const int j0  = blockIdx.x * 8;

    // ---- stage this block's 32 W_h columns into smem (once) ----
    for (int idx = tid; idx < 32768; idx += 256) {
        int k  = idx >> 5;
        int lc = idx & 31;
        ws[idx] = Wh[(size_t)k * G4H + (lc >> 3) * Hh + j0 + (lc & 7)];
    }

    // ---- compute-phase mapping: col pair + 4-row group ----
    const int cg   = tid & 15;          // col pair index (cols 2cg, 2cg+1)
    const int rg   = tid >> 4;          // row group (rows 4rg..4rg+3)
    const int colp = cg * 2;
    const int gate = colp >> 3;
    const int gcol = gate * Hh + j0 + (colp & 7);   // global W_h / xp column
    const int rg4  = rg * 4;

    // ---- staging mapping ----
    const int m4s = (tid & 15) * 4;
    const int ks  = tid >> 4;

    uint32_t sbase;
    asm("{ .reg .u64 t; cvta.to.shared.u64 t, %1; cvt.u32.u64 %0, t; }"
        : "=r"(sbase) : "l"(smem));
    const uint32_t a_base = sbase + 131072u + (uint32_t)rg * 16u;  // sh[kk][rg4], +kk*256
    const uint32_t w_base = sbase + (uint32_t)cg * 8u;             // ws[k][2cg], +k*128

    // ---- gate-phase mapping: this thread owns elements p=tid, p=tid+256 ----
    const int gm0 = tid >> 3;           // batch row 0..31
    const int gjj = tid & 7;            // unit within block
    const int gm1 = gm0 + 32;           // batch row 32..63
    float cc0 = 0.f, cc1 = 0.f;         // cell state in registers

    __syncthreads();

    for (int t = 0; t < Tt; t++) {
        const float* __restrict__ hin  = g_hT[t & 1];
        float* __restrict__       hout = g_hT[(t + 1) & 1];

        // prefetch x_proj contributions (land during K loop)
        float2 xv[4];
#pragma unroll
        for (int i = 0; i < 4; i++)
            xv[i] = *(const float2*)(g_xp + ((size_t)(rg4 + i) * Tt + t) * G4H + gcol);

        // preload h chunk 0
        float4 nxt[4];
#pragma unroll
        for (int r = 0; r < 4; r++)
            nxt[r] = *(const float4*)(hin + (ks + 16 * r) * Bq + m4s);

        uint64_t acc00 = 0ull, acc01 = 0ull, acc10 = 0ull, acc11 = 0ull;

        for (int c = 0; c < 16; c++) {
            __syncthreads();
#pragma unroll
            for (int r = 0; r < 4; r++)
                *(float4*)&sh[(ks + 16 * r) * 64 + m4s] = nxt[r];
            __syncthreads();
            if (c < 15) {
                const float* hp = hin + (c + 1) * 64 * Bq;
#pragma unroll
                for (int r = 0; r < 4; r++)
                    nxt[r] = *(const float4*)(hp + (ks + 16 * r) * Bq + m4s);
            }
            const uint32_t wb = w_base + (uint32_t)(c * 64) * 128u;
#pragma unroll 16
            for (int kk = 0; kk < 64; kk++) {
                uint64_t a01, a23;
                asm volatile("ld.shared.v2.b64 {%0, %1}, [%2];"
                             : "=l"(a01), "=l"(a23)
                             : "r"(a_base + (uint32_t)kk * 256u));
                float w0, w1;
                asm volatile("ld.shared.v2.f32 {%0, %1}, [%2];"
                             : "=f"(w0), "=f"(w1)
                             : "r"(wb + (uint32_t)kk * 128u));
                uint64_t wd0, wd1;
                asm("mov.b64 %0, {%1, %1};" : "=l"(wd0) : "f"(w0));
                asm("mov.b64 %0, {%1, %1};" : "=l"(wd1) : "f"(w1));
                asm("fma.rn.f32x2 %0, %1, %2, %0;" : "+l"(acc00) : "l"(a01), "l"(wd0));
                asm("fma.rn.f32x2 %0, %1, %2, %0;" : "+l"(acc01) : "l"(a01), "l"(wd1));
                asm("fma.rn.f32x2 %0, %1, %2, %0;" : "+l"(acc10) : "l"(a23), "l"(wd0));
                asm("fma.rn.f32x2 %0, %1, %2, %0;" : "+l"(acc11) : "l"(a23), "l"(wd1));
            }
        }

        // unpack accumulators, add x_proj, stash z tile
        float z00, z10, z01, z11, z20, z30, z21, z31;
        asm("mov.b64 {%0, %1}, %2;" : "=f"(z00), "=f"(z10) : "l"(acc00));
        asm("mov.b64 {%0, %1}, %2;" : "=f"(z01), "=f"(z11) : "l"(acc01));
        asm("mov.b64 {%0, %1}, %2;" : "=f"(z20), "=f"(z30) : "l"(acc10));
        asm("mov.b64 {%0, %1}, %2;" : "=f"(z21), "=f"(z31) : "l"(acc11));
        zs[(rg4 + 0) * 34 + colp]     = z00 + xv[0].x;
        zs[(rg4 + 1) * 34 + colp]     = z10 + xv[1].x;
        zs[(rg4 + 0) * 34 + colp + 1] = z01 + xv[0].y;
        zs[(rg4 + 1) * 34 + colp + 1] = z11 + xv[1].y;
        zs[(rg4 + 2) * 34 + colp]     = z20 + xv[2].x;
        zs[(rg4 + 3) * 34 + colp]     = z30 + xv[3].x;
        zs[(rg4 + 2) * 34 + colp + 1] = z21 + xv[2].y;
        zs[(rg4 + 3) * 34 + colp + 1] = z31 + xv[3].y;
        __syncthreads();

        // gate update: 2 elements per thread, c in registers
        {
            float zi = zs[gm0 * 34 + gjj];
            float zf = zs[gm0 * 34 + 8 + gjj];
            float zg = zs[gm0 * 34 + 16 + gjj];
            float zo = zs[gm0 * 34 + 24 + gjj];
            float ig = 1.f / (1.f + __expf(-zi));
            float fg = 1.f / (1.f + __expf(-zf));
            float gg = tanhf(zg);
            float og = 1.f / (1.f + __expf(-zo));
            cc0 = fg * cc0 + ig * gg;
            hout[(j0 + gjj) * Bq + gm0] = og * tanhf(cc0);
        }
        {
            float zi = zs[gm1 * 34 + gjj];
            float zf = zs[gm1 * 34 + 8 + gjj];
            float zg = zs[gm1 * 34 + 16 + gjj];
            float zo = zs[gm1 * 34 + 24 + gjj];
            float ig = 1.f / (1.f + __expf(-zi));
            float fg = 1.f / (1.f + __expf(-zf));
            float gg = tanhf(zg);
            float og = 1.f / (1.f + __expf(-zo));
            cc1 = fg * cc1 + ig * gg;
            hout[(j0 + gjj) * Bq + gm1] = og * tanhf(cc1);
        }

        // grid barrier: all 128 blocks finish step t before t+1 reads hout
        __threadfence();
        __syncthreads();
        if (tid == 0) {
            atomicAdd(&g_bar, 1u);
            unsigned target = (unsigned)NBLK * (unsigned)(t + 1);
            while (*(volatile unsigned*)&g_bar < target) { }
            __threadfence();
        }
        __syncthreads();
    }
}

// =====================================================================
// Kernel 3: hid = relu(h @ Wd1 + bd1)   (h now transposed [k][m])
// =====================================================================
__global__ __launch_bounds__(256) void k_hid(const float* __restrict__ Wd1,
                                             const float* __restrict__ bd1)
{
    const int gid = blockIdx.x * 256 + threadIdx.x;   // 0..32767
    const int m = gid >> 9;
    const int q = gid & 511;
    const float* __restrict__ hT = g_hT[0];           // final h lands in buf 0
    float s = bd1[q];
#pragma unroll 8
    for (int k = 0; k < Hh; k++)
        s = fmaf(hT[k * Bq + m], Wd1[(size_t)k * HD + q], s);
    g_hid[gid] = fmaxf(s, 0.f);
}

// =====================================================================
// Kernel 4: out = [hid, actions, horizon] @ Wd2 + bd2   [64, 64]
// =====================================================================
__global__ __launch_bounds__(256) void k_out(const float* __restrict__ actions,
                                             const float* __restrict__ horizon,
                                             const float* __restrict__ Wd2,
                                             const float* __restrict__ bd2,
                                             float* __restrict__ out)
{
    const int gid = blockIdx.x * 256 + threadIdx.x;   // 0..4095
    const int m = gid >> 6;
    const int n = gid & 63;
    float s = bd2[n];
#pragma unroll 8
    for (int q = 0; q < HD; q++)
        s = fmaf(g_hid[m * HD + q], Wd2[q * NOUT + n], s);
#pragma unroll
    for (int a = 0; a < Aa; a++)
        s = fmaf(actions[m * Aa + a], Wd2[(HD + a) * NOUT + n], s);
    s = fmaf(horizon[m], Wd2[(HD + Aa) * NOUT + n], s);
    out[gid] = s;
}

// =====================================================================
extern "C" void kernel_launch(void* const* d_in, const int* in_sizes, int n_in,
                              void* d_out, int out_size)
{
    const float* x       = (const float*)d_in[0];
    const float* actions = (const float*)d_in[1];
    const float* horizon = (const float*)d_in[2];
    const float* Wx      = (const float*)d_in[3];
    const float* Wh      = (const float*)d_in[4];
    const float* b       = (const float*)d_in[5];
    const float* Wd1     = (const float*)d_in[6];
    const float* bd1     = (const float*)d_in[7];
    const float* Wd2     = (const float*)d_in[8];
    const float* bd2     = (const float*)d_in[9];
    float* out = (float*)d_out;

    cudaFuncSetAttribute(k_persist, cudaFuncAttributeMaxDynamicSharedMemorySize,
                         SMEM_BYTES);

    void *pH = nullptr, *pB = nullptr;
    cudaGetSymbolAddress(&pH, g_hT);
    cudaGetSymbolAddress(&pB, g_bar);
    cudaMemsetAsync(pH, 0, (size_t)Hh * Bq * sizeof(float));   // zero h buffer 0
    cudaMemsetAsync(pB, 0, sizeof(unsigned));                  // reset barrier

    dim3 gx(G4H / 64, MROWS / 64);   // (64, 256)
    k_xproj<<<gx, 256>>>(x, Wx, b);

    k_persist<<<NBLK, 256, SMEM_BYTES>>>(Wh);

    k_hid<<<128, 256>>>(Wd1, bd1);
    k_out<<<16, 256>>>(actions, horizon, Wd2, bd2, out);
}

// round 13
// speedup vs baseline: 1.2112x; 1.2112x over previous
#include <cuda_runtime.h>
#include <cuda_fp16.h>
#include <mma.h>
#include <math.h>
#include <stdint.h>

using namespace nvcuda;

// Problem constants
#define Bq   64
#define Tt   256
#define Ss   512
#define Hh   1024
#define G4H  4096
#define HD   512
#define Aa   64
#define NOUT 64
#define MROWS (Bq * Tt)   // 16384
#define NBLK 128

// ---------------- scratch (device globals; no runtime allocation) ----------
__device__ float  g_xp[(size_t)MROWS * G4H];   // [B*T, 4H] x@W_x (bias added later)
__device__ __half g_xh[(size_t)MROWS * Ss];    // x in fp16 [16384, 512]
__device__ __half g_wxT[(size_t)G4H * Ss];     // W_x^T in fp16 [4096, 512] (K-contig rows)
__device__ float  g_hT[2][Hh * Bq];            // ping-pong hidden state, TRANSPOSED [k][m]
__device__ float  g_hid[Bq * HD];              // relu dense head
__device__ unsigned g_bar;                     // grid barrier counter

// =====================================================================
// Conversion: x (fp32) -> g_xh (fp16), same layout [16384, 512]
// =====================================================================
__global__ __launch_bounds__(256) void k_cvt_x(const float* __restrict__ X)
{
    size_t i = ((size_t)blockIdx.x * 256 + threadIdx.x) * 4;
    float4 v = *(const float4*)(X + i);
    __half2 a = __floats2half2_rn(v.x, v.y);
    __half2 b = __floats2half2_rn(v.z, v.w);
    *(__half2*)(g_xh + i)     = a;
    *(__half2*)(g_xh + i + 2) = b;
}

// =====================================================================
// Conversion: W_x [512, 4096] fp32 -> g_wxT [4096, 512] fp16 (transpose)
// =====================================================================
__global__ __launch_bounds__(256) void k_cvt_wT(const float* __restrict__ Wx)
{
    __shared__ float t[32][33];
    const int nb = blockIdx.x * 32;   // n tile
    const int kb = blockIdx.y * 32;   // k tile
    const int tx = threadIdx.x & 31;
    const int ty = threadIdx.x >> 5;  // 0..7
#pragma unroll
    for (int r = ty; r < 32; r += 8)
        t[r][tx] = Wx[(size_t)(kb + r) * G4H + nb + tx];
    __syncthreads();
#pragma unroll
    for (int r = ty; r < 32; r += 8)
        g_wxT[(size_t)(nb + r) * Ss + kb + tx] = __float2half_rn(t[tx][r]);
}

// =====================================================================
// Kernel 1: x_proj = x @ W_x via wmma (HMMA fp16, fp32 accumulate).
// Block tile 128x128, BK=32, 8 warps (2m x 4n), warp tile 64x32.
// Bias is NOT added here (folded into k_persist).
// =====================================================================
#define BM 128
#define BN 128
#define BK 32
#define LDS_PAD 8
#define LDSB (BK + LDS_PAD)   // 40 halfs = 80 bytes (multiple of 16B)

__global__ __launch_bounds__(256) void k_xproj_mma()
{
    __shared__ __half sA[BM][LDSB];
    __shared__ __half sB[BN][LDSB];

    const int tid = threadIdx.x;
    const int wid = tid >> 5;
    const int wm  = wid & 1;          // warp m index (0..1)  -> 64 rows
    const int wn  = wid >> 1;         // warp n index (0..3)  -> 32 cols
    const int bm  = blockIdx.y * BM;
    const int bn  = blockIdx.x * BN;

    wmma::fragment<wmma::accumulator, 16, 16, 16, float> acc[4][2];
#pragma unroll
    for (int i = 0; i < 4; i++)
#pragma unroll
        for (int j = 0; j < 2; j++)
            wmma::fill_fragment(acc[i][j], 0.0f);

    // staging mapping: each thread copies 16 halfs of A and 16 of B
    const int sr = tid >> 1;               // row 0..127
    const int sc = (tid & 1) * 16;         // col 0 or 16

    for (int k0 = 0; k0 < Ss; k0 += BK) {
        __syncthreads();   // protect previous iteration's fragment reads
        {
            const uint4* sa = (const uint4*)(g_xh  + (size_t)(bm + sr) * Ss + k0 + sc);
            *(uint4*)&sA[sr][sc]     = sa[0];
            *(uint4*)&sA[sr][sc + 8] = sa[1];
            const uint4* sb = (const uint4*)(g_wxT + (size_t)(bn + sr) * Ss + k0 + sc);
            *(uint4*)&sB[sr][sc]     = sb[0];
            *(uint4*)&sB[sr][sc + 8] = sb[1];
        }
        __syncthreads();

#pragma unroll
        for (int kk = 0; kk < BK; kk += 16) {
            wmma::fragment<wmma::matrix_a, 16, 16, 16, __half, wmma::row_major> af[4];
            wmma::fragment<wmma::matrix_b, 16, 16, 16, __half, wmma::col_major> bf[2];
#pragma unroll
            for (int i = 0; i < 4; i++)
                wmma::load_matrix_sync(af[i], &sA[wm * 64 + i * 16][kk], LDSB);
#pragma unroll
            for (int j = 0; j < 2; j++)
                wmma::load_matrix_sync(bf[j], &sB[wn * 32 + j * 16][kk], LDSB);
#pragma unroll
            for (int i = 0; i < 4; i++)
#pragma unroll
                for (int j = 0; j < 2; j++)
                    wmma::mma_sync(acc[i][j], af[i], bf[j], acc[i][j]);
        }
    }

    // store accumulators straight to g_xp (row-major, ldm = 4096)
#pragma unroll
    for (int i = 0; i < 4; i++)
#pragma unroll
        for (int j = 0; j < 2; j++)
            wmma::store_matrix_sync(
                g_xp + (size_t)(bm + wm * 64 + i * 16) * G4H + bn + wn * 32 + j * 16,
                acc[i][j], G4H, wmma::mem_row_major);
}

// =====================================================================
// Kernel 2: persistent LSTM recurrence (R11 passing version + bias fold)
// =====================================================================
#define SMEM_FLOATS 39040
#define SMEM_BYTES  (SMEM_FLOATS * 4)

__global__ __launch_bounds__(256, 1) void k_persist(const float* __restrict__ Wh,
                                                    const float* __restrict__ bias)
{
    extern __shared__ float smem[];
    float* ws = smem;              // [1024][32]
    float* sh = smem + 32768;      // [64][64]  h chunk, [k][m]
    float* zs = smem + 36864;      // [64][34]  z tile, padded

    const int tid = threadIdx.x;
    const int j0  = blockIdx.x * 8;

    for (int idx = tid; idx < 32768; idx += 256) {
        int k  = idx >> 5;
        int lc = idx & 31;
        ws[idx] = Wh[(size_t)k * G4H + (lc >> 3) * Hh + j0 + (lc & 7)];
    }

    const int cg   = tid & 15;
    const int rg   = tid >> 4;
    const int colp = cg * 2;
    const int gate = colp >> 3;
    const int gcol = gate * Hh + j0 + (colp & 7);
    const int rg4  = rg * 4;

    // bias for this thread's two columns (folded out of the GEMM epilogue)
    const float2 bb = *(const float2*)(bias + gcol);

    const int m4s = (tid & 15) * 4;
    const int ks  = tid >> 4;

    uint32_t sbase;
    asm("{ .reg .u64 t; cvta.to.shared.u64 t, %1; cvt.u32.u64 %0, t; }"
        : "=r"(sbase) : "l"(smem));
    const uint32_t a_base = sbase + 131072u + (uint32_t)rg * 16u;
    const uint32_t w_base = sbase + (uint32_t)cg * 8u;

    const int gm0 = tid >> 3;
    const int gjj = tid & 7;
    const int gm1 = gm0 + 32;
    float cc0 = 0.f, cc1 = 0.f;

    __syncthreads();

    for (int t = 0; t < Tt; t++) {
        const float* __restrict__ hin  = g_hT[t & 1];
        float* __restrict__       hout = g_hT[(t + 1) & 1];

        float2 xv[4];
#pragma unroll
        for (int i = 0; i < 4; i++)
            xv[i] = *(const float2*)(g_xp + ((size_t)(rg4 + i) * Tt + t) * G4H + gcol);

        float4 nxt[4];
#pragma unroll
        for (int r = 0; r < 4; r++)
            nxt[r] = *(const float4*)(hin + (ks + 16 * r) * Bq + m4s);

        uint64_t acc00 = 0ull, acc01 = 0ull, acc10 = 0ull, acc11 = 0ull;

        for (int c = 0; c < 16; c++) {
            __syncthreads();
#pragma unroll
            for (int r = 0; r < 4; r++)
                *(float4*)&sh[(ks + 16 * r) * 64 + m4s] = nxt[r];
            __syncthreads();
            if (c < 15) {
                const float* hp = hin + (c + 1) * 64 * Bq;
#pragma unroll
                for (int r = 0; r < 4; r++)
                    nxt[r] = *(const float4*)(hp + (ks + 16 * r) * Bq + m4s);
            }
            const uint32_t wb = w_base + (uint32_t)(c * 64) * 128u;
#pragma unroll 16
            for (int kk = 0; kk < 64; kk++) {
                uint64_t a01, a23;
                asm volatile("ld.shared.v2.b64 {%0, %1}, [%2];"
                             : "=l"(a01), "=l"(a23)
                             : "r"(a_base + (uint32_t)kk * 256u));
                float w0, w1;
                asm volatile("ld.shared.v2.f32 {%0, %1}, [%2];"
                             : "=f"(w0), "=f"(w1)
                             : "r"(wb + (uint32_t)kk * 128u));
                uint64_t wd0, wd1;
                asm("mov.b64 %0, {%1, %1};" : "=l"(wd0) : "f"(w0));
                asm("mov.b64 %0, {%1, %1};" : "=l"(wd1) : "f"(w1));
                asm("fma.rn.f32x2 %0, %1, %2, %0;" : "+l"(acc00) : "l"(a01), "l"(wd0));
                asm("fma.rn.f32x2 %0, %1, %2, %0;" : "+l"(acc01) : "l"(a01), "l"(wd1));
                asm("fma.rn.f32x2 %0, %1, %2, %0;" : "+l"(acc10) : "l"(a23), "l"(wd0));
                asm("fma.rn.f32x2 %0, %1, %2, %0;" : "+l"(acc11) : "l"(a23), "l"(wd1));
            }
        }

        float z00, z10, z01, z11, z20, z30, z21, z31;
        asm("mov.b64 {%0, %1}, %2;" : "=f"(z00), "=f"(z10) : "l"(acc00));
        asm("mov.b64 {%0, %1}, %2;" : "=f"(z01), "=f"(z11) : "l"(acc01));
        asm("mov.b64 {%0, %1}, %2;" : "=f"(z20), "=f"(z30) : "l"(acc10));
        asm("mov.b64 {%0, %1}, %2;" : "=f"(z21), "=f"(z31) : "l"(acc11));
        zs[(rg4 + 0) * 34 + colp]     = z00 + xv[0].x + bb.x;
        zs[(rg4 + 1) * 34 + colp]     = z10 + xv[1].x + bb.x;
        zs[(rg4 + 0) * 34 + colp + 1] = z01 + xv[0].y + bb.y;
        zs[(rg4 + 1) * 34 + colp + 1] = z11 + xv[1].y + bb.y;
        zs[(rg4 + 2) * 34 + colp]     = z20 + xv[2].x + bb.x;
        zs[(rg4 + 3) * 34 + colp]     = z30 + xv[3].x + bb.x;
        zs[(rg4 + 2) * 34 + colp + 1] = z21 + xv[2].y + bb.y;
        zs[(rg4 + 3) * 34 + colp + 1] = z31 + xv[3].y + bb.y;
        __syncthreads();

        {
            float zi = zs[gm0 * 34 + gjj];
            float zf = zs[gm0 * 34 + 8 + gjj];
            float zg = zs[gm0 * 34 + 16 + gjj];
            float zo = zs[gm0 * 34 + 24 + gjj];
            float ig = 1.f / (1.f + __expf(-zi));
            float fg = 1.f / (1.f + __expf(-zf));
            float gg = tanhf(zg);
            float og = 1.f / (1.f + __expf(-zo));
            cc0 = fg * cc0 + ig * gg;
            hout[(j0 + gjj) * Bq + gm0] = og * tanhf(cc0);
        }
        {
            float zi = zs[gm1 * 34 + gjj];
            float zf = zs[gm1 * 34 + 8 + gjj];
            float zg = zs[gm1 * 34 + 16 + gjj];
            float zo = zs[gm1 * 34 + 24 + gjj];
            float ig = 1.f / (1.f + __expf(-zi));
            float fg = 1.f / (1.f + __expf(-zf));
            float gg = tanhf(zg);
            float og = 1.f / (1.f + __expf(-zo));
            cc1 = fg * cc1 + ig * gg;
            hout[(j0 + gjj) * Bq + gm1] = og * tanhf(cc1);
        }

        __threadfence();
        __syncthreads();
        if (tid == 0) {
            atomicAdd(&g_bar, 1u);
            unsigned target = (unsigned)NBLK * (unsigned)(t + 1);
            while (*(volatile unsigned*)&g_bar < target) { }
            __threadfence();
        }
        __syncthreads();
    }
}

// =====================================================================
// Kernel 3: hid = relu(h @ Wd1 + bd1)   (h transposed [k][m])
// =====================================================================
__global__ __launch_bounds__(256) void k_hid(const float* __restrict__ Wd1,
                                             const float* __restrict__ bd1)
{
    const int gid = blockIdx.x * 256 + threadIdx.x;
    const int m = gid >> 9;
    const int q = gid & 511;
    const float* __restrict__ hT = g_hT[0];
    float s = bd1[q];
#pragma unroll 8
    for (int k = 0; k < Hh; k++)
        s = fmaf(hT[k * Bq + m], Wd1[(size_t)k * HD + q], s);
    g_hid[gid] = fmaxf(s, 0.f);
}

// =====================================================================
// Kernel 4: out = [hid, actions, horizon] @ Wd2 + bd2   [64, 64]
// =====================================================================
__global__ __launch_bounds__(256) void k_out(const float* __restrict__ actions,
                                             const float* __restrict__ horizon,
                                             const float* __restrict__ Wd2,
                                             const float* __restrict__ bd2,
                                             float* __restrict__ out)
{
    const int gid = blockIdx.x * 256 + threadIdx.x;
    const int m = gid >> 6;
    const int n = gid & 63;
    float s = bd2[n];
#pragma unroll 8
    for (int q = 0; q < HD; q++)
        s = fmaf(g_hid[m * HD + q], Wd2[q * NOUT + n], s);
#pragma unroll
    for (int a = 0; a < Aa; a++)
        s = fmaf(actions[m * Aa + a], Wd2[(HD + a) * NOUT + n], s);
    s = fmaf(horizon[m], Wd2[(HD + Aa) * NOUT + n], s);
    out[gid] = s;
}

// =====================================================================
extern "C" void kernel_launch(void* const* d_in, const int* in_sizes, int n_in,
                              void* d_out, int out_size)
{
    const float* x       = (const float*)d_in[0];
    const float* actions = (const float*)d_in[1];
    const float* horizon = (const float*)d_in[2];
    const float* Wx      = (const float*)d_in[3];
    const float* Wh      = (const float*)d_in[4];
    const float* b       = (const float*)d_in[5];
    const float* Wd1     = (const float*)d_in[6];
    const float* bd1     = (const float*)d_in[7];
    const float* Wd2     = (const float*)d_in[8];
    const float* bd2     = (const float*)d_in[9];
    float* out = (float*)d_out;

    cudaFuncSetAttribute(k_persist, cudaFuncAttributeMaxDynamicSharedMemorySize,
                         SMEM_BYTES);

    void *pH = nullptr, *pB = nullptr;
    cudaGetSymbolAddress(&pH, g_hT);
    cudaGetSymbolAddress(&pB, g_bar);
    cudaMemsetAsync(pH, 0, (size_t)Hh * Bq * sizeof(float));   // zero h buffer 0
    cudaMemsetAsync(pB, 0, sizeof(unsigned));                  // reset barrier

    // fp16 conversions
    k_cvt_x<<<(MROWS * Ss) / (256 * 4), 256>>>(x);
    k_cvt_wT<<<dim3(G4H / 32, Ss / 32), 256>>>(Wx);

    // x_proj on tensor cores (HMMA via wmma; bias folded into k_persist)
    k_xproj_mma<<<dim3(G4H / BN, MROWS / BM), 256>>>();

    k_persist<<<NBLK, 256, SMEM_BYTES>>>(Wh, b);

    k_hid<<<128, 256>>>(Wd1, bd1);
    k_out<<<16, 256>>>(actions, horizon, Wd2, bd2, out);
}

// round 14
// speedup vs baseline: 3.5349x; 2.9184x over previous
#include <cuda_runtime.h>
#include <cuda_fp16.h>
#include <mma.h>
#include <math.h>
#include <stdint.h>

using namespace nvcuda;

// Problem constants
#define Bq   64
#define Tt   256
#define Ss   512
#define Hh   1024
#define G4H  4096
#define HD   512
#define Aa   64
#define NOUT 64
#define MROWS (Bq * Tt)   // 16384
#define NBLK 128

// ---------------- scratch (device globals; no runtime allocation) ----------
__device__ float  g_xp[(size_t)MROWS * G4H];   // [B*T, 4H] x@W_x (bias folded later)
__device__ __half g_xh[(size_t)MROWS * Ss];    // x in fp16 [16384, 512]
__device__ __half g_wxT[(size_t)G4H * Ss];     // W_x^T in fp16 [4096, 512]
__device__ __half g_h16[2][Bq * Hh];           // ping-pong hidden state fp16, [m][k]
__device__ float  g_hid[Bq * HD];              // relu dense head
__device__ unsigned g_bar;                     // grid barrier counter

// =====================================================================
// Conversion: x (fp32) -> g_xh (fp16)
// =====================================================================
__global__ __launch_bounds__(256) void k_cvt_x(const float* __restrict__ X)
{
    size_t i = ((size_t)blockIdx.x * 256 + threadIdx.x) * 4;
    float4 v = *(const float4*)(X + i);
    *(__half2*)(g_xh + i)     = __floats2half2_rn(v.x, v.y);
    *(__half2*)(g_xh + i + 2) = __floats2half2_rn(v.z, v.w);
}

// =====================================================================
// Conversion: W_x [512, 4096] fp32 -> g_wxT [4096, 512] fp16 (transpose)
// =====================================================================
__global__ __launch_bounds__(256) void k_cvt_wT(const float* __restrict__ Wx)
{
    __shared__ float t[32][33];
    const int nb = blockIdx.x * 32;
    const int kb = blockIdx.y * 32;
    const int tx = threadIdx.x & 31;
    const int ty = threadIdx.x >> 5;
#pragma unroll
    for (int r = ty; r < 32; r += 8)
        t[r][tx] = Wx[(size_t)(kb + r) * G4H + nb + tx];
    __syncthreads();
#pragma unroll
    for (int r = ty; r < 32; r += 8)
        g_wxT[(size_t)(nb + r) * Ss + kb + tx] = __float2half_rn(t[tx][r]);
}

// =====================================================================
// Kernel 1: x_proj = x @ W_x via wmma (HMMA fp16, fp32 accumulate).
// Block tile 128x128, BK=32, 8 warps (2m x 4n), warp tile 64x32.
// =====================================================================
#define BM 128
#define BN 128
#define BK 32
#define LDSB (BK + 8)   // 40 halfs = 80 bytes

__global__ __launch_bounds__(256) void k_xproj_mma()
{
    __shared__ __half sA[BM][LDSB];
    __shared__ __half sB[BN][LDSB];

    const int tid = threadIdx.x;
    const int wid = tid >> 5;
    const int wm  = wid & 1;
    const int wn  = wid >> 1;
    const int bm  = blockIdx.y * BM;
    const int bn  = blockIdx.x * BN;

    wmma::fragment<wmma::accumulator, 16, 16, 16, float> acc[4][2];
#pragma unroll
    for (int i = 0; i < 4; i++)
#pragma unroll
        for (int j = 0; j < 2; j++)
            wmma::fill_fragment(acc[i][j], 0.0f);

    const int sr = tid >> 1;
    const int sc = (tid & 1) * 16;

    for (int k0 = 0; k0 < Ss; k0 += BK) {
        __syncthreads();
        {
            const uint4* sa = (const uint4*)(g_xh  + (size_t)(bm + sr) * Ss + k0 + sc);
            *(uint4*)&sA[sr][sc]     = sa[0];
            *(uint4*)&sA[sr][sc + 8] = sa[1];
            const uint4* sb = (const uint4*)(g_wxT + (size_t)(bn + sr) * Ss + k0 + sc);
            *(uint4*)&sB[sr][sc]     = sb[0];
            *(uint4*)&sB[sr][sc + 8] = sb[1];
        }
        __syncthreads();

#pragma unroll
        for (int kk = 0; kk < BK; kk += 16) {
            wmma::fragment<wmma::matrix_a, 16, 16, 16, __half, wmma::row_major> af[4];
            wmma::fragment<wmma::matrix_b, 16, 16, 16, __half, wmma::col_major> bf[2];
#pragma unroll
            for (int i = 0; i < 4; i++)
                wmma::load_matrix_sync(af[i], &sA[wm * 64 + i * 16][kk], LDSB);
#pragma unroll
            for (int j = 0; j < 2; j++)
                wmma::load_matrix_sync(bf[j], &sB[wn * 32 + j * 16][kk], LDSB);
#pragma unroll
            for (int i = 0; i < 4; i++)
#pragma unroll
                for (int j = 0; j < 2; j++)
                    wmma::mma_sync(acc[i][j], af[i], bf[j], acc[i][j]);
        }
    }

#pragma unroll
    for (int i = 0; i < 4; i++)
#pragma unroll
        for (int j = 0; j < 2; j++)
            wmma::store_matrix_sync(
                g_xp + (size_t)(bm + wm * 64 + i * 16) * G4H + bn + wn * 32 + j * 16,
                acc[i][j], G4H, wmma::mem_row_major);
}

// =====================================================================
// Kernel 2: persistent LSTM recurrence on tensor cores.
// 128 blocks x 256 threads. Block b owns 8 hidden units (32 z-columns,
// gate-major c = gate*8+jj). W_h columns in smem fp16 col-major (once).
// Per step: stage fp16 h [64][1024] in 4 chunks of 256, 8 warps each do
// one 16x16 wmma tile of the 64x32 z-tile, fp32 accum -> zs smem ->
// gate math (xp + bias folded here) -> fp16 h out, grid barrier.
// =====================================================================
#define WS_LD 1032
#define SH_LD 264
#define ZS_LD 40
// smem bytes: wsB 32*1032*2 = 66048 ; shh 64*264*2 = 33792 ; zs 64*40*4 = 10240
#define P_WS_OFF  0
#define P_SH_OFF  66048
#define P_ZS_OFF  (66048 + 33792)
#define P_SMEM    (66048 + 33792 + 10240)

__global__ __launch_bounds__(256, 1) void k_persist(const float* __restrict__ Wh,
                                                    const float* __restrict__ bias)
{
    extern __shared__ char psm[];
    __half* wsB = (__half*)(psm + P_WS_OFF);   // [32][1032] col-major W_h fp16
    __half* shh = (__half*)(psm + P_SH_OFF);   // [64][264]  h chunk fp16
    float*  zsf = (float*)(psm + P_ZS_OFF);    // [64][40]   z tile fp32

    const int tid = threadIdx.x;
    const int j0  = blockIdx.x * 8;

    // ---- stage this block's 32 W_h columns as fp16 (once) ----
    for (int idx = tid; idx < 32768; idx += 256) {
        int c = idx & 31, k = idx >> 5;
        wsB[c * WS_LD + k] =
            __float2half_rn(Wh[(size_t)k * G4H + (c >> 3) * Hh + j0 + (c & 7)]);
    }

    // ---- warp tile mapping (8 warps -> 4 row tiles x 2 col tiles) ----
    const int w  = tid >> 5;
    const int rt = w & 3;          // rows rt*16..+15
    const int ct = w >> 2;         // cols ct*16..+15
    const int L  = tid & 31;

    // ---- h staging mapping: lanes 0-7 of a phase cover one contiguous
    //      128B row segment (conflict-free STS.128 / coalesced LDG) ----
    const int srow = (w << 3) + (L >> 3);   // + p*4, p in {0,1}
    const int scol = (L & 7) * 8;           // halfs

    // ---- gate mapping ----
    const int gjj = tid & 7;
    const int gm0 = tid >> 3;      // 0..31
    const int gm1 = gm0 + 32;
    float bb[4];
#pragma unroll
    for (int g = 0; g < 4; g++) bb[g] = bias[g * Hh + j0 + gjj];

    float cc0 = 0.f, cc1 = 0.f;
    __syncthreads();

    for (int t = 0; t < Tt; t++) {
        const __half* __restrict__ hin  = g_h16[t & 1];
        __half* __restrict__       hout = g_h16[(t + 1) & 1];

        // prefetch xp for the gate phase (consumed after the MMAs)
        float xg0[4], xg1[4];
#pragma unroll
        for (int g = 0; g < 4; g++) {
            const size_t cb = (size_t)g * Hh + j0 + gjj;
            xg0[g] = g_xp[(size_t)(gm0 * Tt + t) * G4H + cb];
            xg1[g] = g_xp[(size_t)(gm1 * Tt + t) * G4H + cb];
        }

        wmma::fragment<wmma::accumulator, 16, 16, 16, float> acc;
        wmma::fill_fragment(acc, 0.0f);

        // preload chunk 0
        uint4 nxt[8];
#pragma unroll
        for (int p = 0; p < 2; p++)
#pragma unroll
            for (int q = 0; q < 4; q++)
                nxt[p * 4 + q] = *(const uint4*)(hin + (size_t)(srow + p * 4) * Hh
                                                 + scol + q * 64);

        for (int ck = 0; ck < 4; ck++) {
            __syncthreads();
#pragma unroll
            for (int p = 0; p < 2; p++)
#pragma unroll
                for (int q = 0; q < 4; q++)
                    *(uint4*)(shh + (srow + p * 4) * SH_LD + scol + q * 64)
                        = nxt[p * 4 + q];
            __syncthreads();
            if (ck < 3) {
                const int k0 = (ck + 1) * 256;
#pragma unroll
                for (int p = 0; p < 2; p++)
#pragma unroll
                    for (int q = 0; q < 4; q++)
                        nxt[p * 4 + q] = *(const uint4*)(hin + (size_t)(srow + p * 4) * Hh
                                                         + k0 + scol + q * 64);
            }
#pragma unroll
            for (int kk = 0; kk < 16; kk++) {
                wmma::fragment<wmma::matrix_a, 16, 16, 16, __half, wmma::row_major> af;
                wmma::fragment<wmma::matrix_b, 16, 16, 16, __half, wmma::col_major> bf;
                wmma::load_matrix_sync(af, shh + rt * 16 * SH_LD + kk * 16, SH_LD);
                wmma::load_matrix_sync(bf, wsB + ct * 16 * WS_LD + ck * 256 + kk * 16, WS_LD);
                wmma::mma_sync(acc, af, bf, acc);
            }
        }

        wmma::store_matrix_sync(zsf + rt * 16 * ZS_LD + ct * 16, acc, ZS_LD,
                                wmma::mem_row_major);
        __syncthreads();

        // gate update, cell state in registers
        {
            float zi = zsf[gm0 * ZS_LD + gjj]      + xg0[0] + bb[0];
            float zf = zsf[gm0 * ZS_LD + 8 + gjj]  + xg0[1] + bb[1];
            float zg = zsf[gm0 * ZS_LD + 16 + gjj] + xg0[2] + bb[2];
            float zo = zsf[gm0 * ZS_LD + 24 + gjj] + xg0[3] + bb[3];
            float ig = 1.f / (1.f + __expf(-zi));
            float fg = 1.f / (1.f + __expf(-zf));
            float gg = tanhf(zg);
            float og = 1.f / (1.f + __expf(-zo));
            cc0 = fg * cc0 + ig * gg;
            hout[(size_t)gm0 * Hh + j0 + gjj] = __float2half_rn(og * tanhf(cc0));
        }
        {
            float zi = zsf[gm1 * ZS_LD + gjj]      + xg1[0] + bb[0];
            float zf = zsf[gm1 * ZS_LD + 8 + gjj]  + xg1[1] + bb[1];
            float zg = zsf[gm1 * ZS_LD + 16 + gjj] + xg1[2] + bb[2];
            float zo = zsf[gm1 * ZS_LD + 24 + gjj] + xg1[3] + bb[3];
            float ig = 1.f / (1.f + __expf(-zi));
            float fg = 1.f / (1.f + __expf(-zf));
            float gg = tanhf(zg);
            float og = 1.f / (1.f + __expf(-zo));
            cc1 = fg * cc1 + ig * gg;
            hout[(size_t)gm1 * Hh + j0 + gjj] = __float2half_rn(og * tanhf(cc1));
        }

        // grid barrier: all 128 blocks finish step t before t+1 reads hout
        __threadfence();
        __syncthreads();
        if (tid == 0) {
            atomicAdd(&g_bar, 1u);
            unsigned target = (unsigned)NBLK * (unsigned)(t + 1);
            while (*(volatile unsigned*)&g_bar < target) { }
            __threadfence();
        }
        __syncthreads();
    }
}

// =====================================================================
// Kernel 3: hid = relu(h @ Wd1 + bd1)   (h fp16 row-major [m][k])
// =====================================================================
__global__ __launch_bounds__(256) void k_hid(const float* __restrict__ Wd1,
                                             const float* __restrict__ bd1)
{
    const int gid = blockIdx.x * 256 + threadIdx.x;
    const int m = gid >> 9;
    const int q = gid & 511;
    const __half* __restrict__ h = g_h16[0] + (size_t)m * Hh;  // final h in buf 0
    float s = bd1[q];
#pragma unroll 4
    for (int k = 0; k < Hh; k += 2) {
        __half2 hv = *(const __half2*)(h + k);
        s = fmaf(__low2float(hv),  Wd1[(size_t)k * HD + q], s);
        s = fmaf(__high2float(hv), Wd1[(size_t)(k + 1) * HD + q], s);
    }
    g_hid[gid] = fmaxf(s, 0.f);
}

// =====================================================================
// Kernel 4: out = [hid, actions, horizon] @ Wd2 + bd2   [64, 64]
// =====================================================================
__global__ __launch_bounds__(256) void k_out(const float* __restrict__ actions,
                                             const float* __restrict__ horizon,
                                             const float* __restrict__ Wd2,
                                             const float* __restrict__ bd2,
                                             float* __restrict__ out)
{
    const int gid = blockIdx.x * 256 + threadIdx.x;
    const int m = gid >> 6;
    const int n = gid & 63;
    float s = bd2[n];
#pragma unroll 8
    for (int q = 0; q < HD; q++)
        s = fmaf(g_hid[m * HD + q], Wd2[q * NOUT + n], s);
#pragma unroll
    for (int a = 0; a < Aa; a++)
        s = fmaf(actions[m * Aa + a], Wd2[(HD + a) * NOUT + n], s);
    s = fmaf(horizon[m], Wd2[(HD + Aa) * NOUT + n], s);
    out[gid] = s;
}

// =====================================================================
extern "C" void kernel_launch(void* const* d_in, const int* in_sizes, int n_in,
                              void* d_out, int out_size)
{
    const float* x       = (const float*)d_in[0];
    const float* actions = (const float*)d_in[1];
    const float* horizon = (const float*)d_in[2];
    const float* Wx      = (const float*)d_in[3];
    const float* Wh      = (const float*)d_in[4];
    const float* b       = (const float*)d_in[5];
    const float* Wd1     = (const float*)d_in[6];
    const float* bd1     = (const float*)d_in[7];
    const float* Wd2     = (const float*)d_in[8];
    const float* bd2     = (const float*)d_in[9];
    float* out = (float*)d_out;

    cudaFuncSetAttribute(k_persist, cudaFuncAttributeMaxDynamicSharedMemorySize,
                         P_SMEM);

    void *pH = nullptr, *pB = nullptr;
    cudaGetSymbolAddress(&pH, g_h16);
    cudaGetSymbolAddress(&pB, g_bar);
    cudaMemsetAsync(pH, 0, (size_t)Bq * Hh * sizeof(__half));  // zero h buffer 0
    cudaMemsetAsync(pB, 0, sizeof(unsigned));                  // reset barrier

    // fp16 conversions
    k_cvt_x<<<(MROWS * Ss) / (256 * 4), 256>>>(x);
    k_cvt_wT<<<dim3(G4H / 32, Ss / 32), 256>>>(Wx);

    // x_proj on tensor cores (bias folded into k_persist)
    k_xproj_mma<<<dim3(G4H / BN, MROWS / BM), 256>>>();

    // recurrence on tensor cores
    k_persist<<<NBLK, 256, P_SMEM>>>(Wh, b);

    k_hid<<<128, 256>>>(Wd1, bd1);
    k_out<<<16, 256>>>(actions, horizon, Wd2, bd2, out);
}